// round 8
// baseline (speedup 1.0000x reference)
#include <cuda_runtime.h>
#include <cstdint>

// Encoder: out[r,0] = x[r]; out[r,1+i] = square(2*pi * x[r] * 2^i), i = 0..14
//
// Exact integer decision (see R4): with t = fl32(2pi*x) = M*2^(e-150) and
// C = fl32(2pi) = Mc*2^-21 (Mc = 13176795), sign for freq i is bit (14-i) of
//   B = floor((t/C) * 2^15) = floor(M * 2^(e-114) / Mc)
// computed exactly via Granlund-Montgomery: MAGIC = ceil(2^63/Mc);
//   B = (M*MAGIC) >> (177-e) for e in [114,129]; else 0.
//
// R8: R7's coalesced stores + MLP, but NO shuffles. Lane L, iteration j
// handles word (L&3) of row rowBase + 8j + L/4, recomputing B locally
// (SHFL was loading the same MIO/L1 pipe the stores saturate; ALU had
// 4x headroom). x loads are 1 sector/warp/iter and L1-hit after the
// first touch of the warp's 128B x line.

namespace {
constexpr float              CF    = 6.28318530717958647692f;  // fl32(2*pi) = Mc*2^-21
constexpr unsigned           MC    = 13176795u;
constexpr unsigned long long MAGIC = (0x8000000000000000ULL + (MC - 1)) / MC;
}

__global__ void __launch_bounds__(256)
Encoder_22668837388855_kernel(const float* __restrict__ x,
                              float4* __restrict__ out4,
                              unsigned n) {
    unsigned lane    = threadIdx.x & 31u;
    unsigned warpGid = (blockIdx.x * blockDim.x + threadIdx.x) >> 5;
    unsigned rowBase = warpGid << 5;            // 32 rows per warp
    if (rowBase >= n) return;                   // n is a multiple of 32

    unsigned sr = lane >> 2;                    // sub-row within 8-row group
    unsigned w  = lane & 3u;                    // word index within row
    unsigned sh = 16u + (w << 2);               // aligns word's first sign slot

    // Front-batched loads: 4 independent LDGs in flight.
    float xv[4];
#pragma unroll
    for (unsigned j = 0; j < 4; j++)
        xv[j] = __ldg(&x[rowBase + (j << 3) + sr]);

#pragma unroll
    for (unsigned j = 0; j < 4; j++) {
        float t = __fmul_rn(CF, xv[j]);         // fl(2pi * x)
        unsigned tb = __float_as_uint(t);
        unsigned e  = tb >> 23;
        unsigned M  = (tb & 0x7FFFFFu) | 0x800000u;
        unsigned long long P = (unsigned long long)M * MAGIC;
        unsigned B = (e >= 114u) ? (unsigned)(P >> (177u - e)) : 0u;

        unsigned bs = B << sh;
        float4 o;
        o.x = __uint_as_float((bs & 0x80000000u) | 0x3F800000u); bs += bs;
        o.y = __uint_as_float((bs & 0x80000000u) | 0x3F800000u); bs += bs;
        o.z = __uint_as_float((bs & 0x80000000u) | 0x3F800000u); bs += bs;
        o.w = __uint_as_float((bs & 0x80000000u) | 0x3F800000u);
        if (w == 0) o.x = xv[j];                // col 0 of each row is raw x

        // word index = (rowBase + 8j + sr)*4 + w = rowBase*4 + j*32 + lane
        __stcs(&out4[(size_t)rowBase * 4 + (size_t)(j << 5) + lane], o);
    }
}

extern "C" void kernel_launch(void* const* d_in, const int* in_sizes, int n_in,
                              void* d_out, int out_size) {
    const float* x = (const float*)d_in[0];
    float4* out = (float4*)d_out;
    unsigned n = (unsigned)in_sizes[0];
    unsigned warps  = (n + 31u) / 32u;
    unsigned total  = warps * 32u;
    int threads = 256;
    unsigned blocks = (total + threads - 1) / threads;
    Encoder_22668837388855_kernel<<<blocks, threads>>>(x, out, n);
}